// round 9
// baseline (speedup 1.0000x reference)
#include <cuda_runtime.h>
#include <cuda_bf16.h>

#define FEAT      4096
#define NTHREADS  512
#define PER       8           // FEAT / NTHREADS
#define SEL_RANK  2048u
#define SLOT_CAP  16

// monotone fp32 -> u32 key (fallback path only)
__device__ __forceinline__ unsigned int fkey(float f) {
    unsigned int u = __float_as_uint(f);
    return u ^ ((unsigned int)((int)u >> 31) | 0x80000000u);
}
__device__ __forceinline__ float kinv(unsigned int k) {
    unsigned int m = (unsigned int)((int)(~k) >> 31) | 0x80000000u;
    return __uint_as_float(k ^ m);
}

// One-warp scan of a 256-bin shared histogram (8 bins/lane): find bin holding
// `rank`. Writes *s_sel / *s_rank only if found (rank may wrap -> not found).
__device__ __forceinline__ void warp_select256(const unsigned int* hist, unsigned int rank,
                                               unsigned int* s_sel, unsigned int* s_rank)
{
    const unsigned int lane = threadIdx.x & 31;
    uint4 a = reinterpret_cast<const uint4*>(hist)[2 * lane];
    uint4 b = reinterpret_cast<const uint4*>(hist)[2 * lane + 1];
    unsigned int c[8] = {a.x, a.y, a.z, a.w, b.x, b.y, b.z, b.w};
    unsigned int csum = c[0]+c[1]+c[2]+c[3]+c[4]+c[5]+c[6]+c[7];
    unsigned int v = csum;
    #pragma unroll
    for (int off = 1; off < 32; off <<= 1) {
        unsigned int t = __shfl_up_sync(0xFFFFFFFFu, v, off);
        if (lane >= (unsigned)off) v += t;
    }
    const unsigned int base = v - csum;
    if (rank - base < csum) {
        unsigned int r = rank - base;
        unsigned int d = lane * 8u;
        #pragma unroll
        for (int i = 0; i < 7; i++) {
            if (r >= c[i]) { r -= c[i]; d++; }
            else break;
        }
        *s_sel  = d;
        *s_rank = r;
    }
}

__global__ __launch_bounds__(NTHREADS, 3)
void MaxoutDynamic_kernel(const float* __restrict__ feat, float* __restrict__ out) {
    __shared__ __align__(16) unsigned int hist[2][256];            // 2 KB
    __shared__ __align__(16) float slots[2][256 * SLOT_CAP];       // 32 KB
    __shared__ unsigned int wsum[16];
    __shared__ unsigned int s_sel[2], s_rank[2], s_state;
    __shared__ float s_T[2];

    const int tid = threadIdx.x;
    const unsigned int lane = tid & 31;
    const unsigned int wid  = tid >> 5;
    const size_t row_off = (size_t)blockIdx.x * (2 * FEAT);

    // ---- load BOTH rows upfront (4 x LDG.128 in flight) ----
    const float4* in4 = reinterpret_cast<const float4*>(feat + row_off);
    float4 a0 = in4[tid];
    float4 a1 = in4[tid + NTHREADS];
    float4 b0 = in4[tid + 2 * NTHREADS];
    float4 b1 = in4[tid + 3 * NTHREADS];

    if (tid < 128) reinterpret_cast<uint4*>(hist)[tid] = make_uint4(0u,0u,0u,0u);
    if (tid < 2)  s_sel[tid] = 0xFFFFFFFFu;
    if (tid == 0) s_state = 0u;
    __syncthreads();   // B1

    float f0[PER] = {a0.x, a0.y, a0.z, a0.w, a1.x, a1.y, a1.z, a1.w};
    float f1[PER] = {b0.x, b0.y, b0.z, b0.w, b1.x, b1.y, b1.z, b1.w};

    // ---- fused binning pass for both rows; below-counts packed lo/hi 16b ----
    // bin(f) = floor(f*1024 + 128): bin<0 <=> f < -0.125; bin in [0,256) covers
    // [-0.125, 0.125) (row-median threshold ~N(0,0.02): 6+ sigma margin)
    unsigned int below = 0;
    #pragma unroll
    for (int e = 0; e < PER; e++) {
        int b0i = __float2int_rd(fmaf(f0[e], 1024.0f, 128.0f));
        below += ((unsigned int)b0i) >> 31;
        if ((unsigned int)b0i < 256u) {
            unsigned int old = atomicAdd(&hist[0][b0i], 1u);
            if (old < SLOT_CAP) slots[0][b0i * SLOT_CAP + old] = f0[e];
        }
        int b1i = __float2int_rd(fmaf(f1[e], 1024.0f, 128.0f));
        below += (((unsigned int)b1i) >> 31) << 16;
        if ((unsigned int)b1i < 256u) {
            unsigned int old = atomicAdd(&hist[1][b1i], 1u);
            if (old < SLOT_CAP) slots[1][b1i * SLOT_CAP + old] = f1[e];
        }
    }
    below = __reduce_add_sync(0xFFFFFFFFu, below);
    if (lane == 0) wsum[wid] = below;
    __syncthreads();   // B2

    // ---- warps 0 and 1 select the two rows' thresholds IN PARALLEL ----
    if (wid < 2) {
        const unsigned int tot =
            __reduce_add_sync(0xFFFFFFFFu, (lane < 16u) ? wsum[lane] : 0u);
        const unsigned int tb = (wid == 0) ? (tot & 0xFFFFu) : (tot >> 16);
        const unsigned int rank0 = SEL_RANK - tb;   // may wrap -> fallback
        warp_select256(hist[wid], rank0, &s_sel[wid], &s_rank[wid]);
        __syncwarp();
        const unsigned int sel = s_sel[wid];
        bool bad = (sel == 0xFFFFFFFFu);
        unsigned int cnt = 0;
        if (!bad) {
            cnt = hist[wid][sel];
            bad = (cnt > SLOT_CAP);
        }
        if (bad) {
            if (lane == 0) atomicOr(&s_state, 1u << wid);
        } else {
            const unsigned int rb = s_rank[wid];
            float fi = (lane < cnt) ? slots[wid][sel * SLOT_CAP + lane] : 0.0f;
            unsigned int cl = 0;
            for (unsigned int j = 0; j < cnt; j++) {
                float fj = __shfl_sync(0xFFFFFFFFu, fi, j);
                cl += (fj < fi) || (fj == fi && j < lane);
            }
            if (lane < cnt && cl == rb) s_T[wid] = fi;   // exactly one winner
        }
    }
    __syncthreads();   // B3

    float T0, T1;
    if (s_state == 0u) {
        T0 = s_T[0];
        T1 = s_T[1];
    } else {
        // ---- general exact fallback (block-uniform, ~never taken):
        //      per failed row, 4-pass 8-bit MSB radix select ----
        #pragma unroll 1
        for (int r = 0; r < 2; r++) {
            float Tr;
            if ((s_state >> r) & 1u) {
                unsigned int key[PER];
                #pragma unroll
                for (int e = 0; e < PER; e++)
                    key[e] = fkey(r ? f1[e] : f0[e]);
                unsigned int prefix = 0u, pmask = 0u, rnk = SEL_RANK;
                for (int p = 0; p < 4; p++) {
                    const int shift = 24 - 8 * p;
                    __syncthreads();
                    if (tid < 64) reinterpret_cast<uint4*>(hist[0])[tid] = make_uint4(0u,0u,0u,0u);
                    if (tid == 0) s_sel[0] = 0xFFFFFFFFu;
                    __syncthreads();
                    #pragma unroll
                    for (int e = 0; e < PER; e++)
                        if ((key[e] & pmask) == prefix)
                            atomicAdd(&hist[0][(key[e] >> shift) & 255u], 1u);
                    __syncthreads();
                    if (wid == 0) warp_select256(hist[0], rnk, &s_sel[0], &s_rank[0]);
                    __syncthreads();
                    prefix |= s_sel[0] << shift;
                    pmask  |= 255u << shift;
                    rnk = s_rank[0];
                }
                Tr = kinv(prefix);
            } else {
                Tr = s_T[r];
            }
            if (r == 0) T0 = Tr; else T1 = Tr;
        }
    }

    // ---- predicated scaled writeback, both rows ----
    float4* out4 = reinterpret_cast<float4*>(out + row_off);
    float4 r0, r1, r2, r3;
    r0.x = (f0[0] >= T0) ? 2.0f * f0[0] : 0.0f;
    r0.y = (f0[1] >= T0) ? 2.0f * f0[1] : 0.0f;
    r0.z = (f0[2] >= T0) ? 2.0f * f0[2] : 0.0f;
    r0.w = (f0[3] >= T0) ? 2.0f * f0[3] : 0.0f;
    r1.x = (f0[4] >= T0) ? 2.0f * f0[4] : 0.0f;
    r1.y = (f0[5] >= T0) ? 2.0f * f0[5] : 0.0f;
    r1.z = (f0[6] >= T0) ? 2.0f * f0[6] : 0.0f;
    r1.w = (f0[7] >= T0) ? 2.0f * f0[7] : 0.0f;
    r2.x = (f1[0] >= T1) ? 2.0f * f1[0] : 0.0f;
    r2.y = (f1[1] >= T1) ? 2.0f * f1[1] : 0.0f;
    r2.z = (f1[2] >= T1) ? 2.0f * f1[2] : 0.0f;
    r2.w = (f1[3] >= T1) ? 2.0f * f1[3] : 0.0f;
    r3.x = (f1[4] >= T1) ? 2.0f * f1[4] : 0.0f;
    r3.y = (f1[5] >= T1) ? 2.0f * f1[5] : 0.0f;
    r3.z = (f1[6] >= T1) ? 2.0f * f1[6] : 0.0f;
    r3.w = (f1[7] >= T1) ? 2.0f * f1[7] : 0.0f;
    out4[tid]                = r0;
    out4[tid +     NTHREADS] = r1;
    out4[tid + 2 * NTHREADS] = r2;
    out4[tid + 3 * NTHREADS] = r3;
}

extern "C" void kernel_launch(void* const* d_in, const int* in_sizes, int n_in,
                              void* d_out, int out_size) {
    const float* feat = (const float*)d_in[0];
    float* out = (float*)d_out;
    const int rows = in_sizes[0] / FEAT;     // 16384
    MaxoutDynamic_kernel<<<rows / 2, NTHREADS>>>(feat, out);
}